// round 3
// baseline (speedup 1.0000x reference)
#include <cuda_runtime.h>
#include <cuda_bf16.h>
#include <cstdint>
#include <cstddef>

#define DINL __device__ __forceinline__

// ============================== device scratch ==============================
__device__ float g_part[64 * 128];        // encoder layer-1 partial sums
__device__ float g_bg[2];                 // beta, gamma
__device__ float g_sol[8192 * 3];         // SIR states [T][3]
__device__ __align__(128) __nv_bfloat16 g_h2_hi[8192 * 128];
__device__ __align__(128) __nv_bfloat16 g_h2_lo[8192 * 128];
__device__ __align__(128) __nv_bfloat16 g_w3t_hi[8192 * 128];  // W3^T [N][K]
__device__ __align__(128) __nv_bfloat16 g_w3t_lo[8192 * 128];

// ============================== encoder =====================================
__global__ void enc1_kernel(const float* __restrict__ x,
                            const float* __restrict__ w1) {
    int j = threadIdx.x;               // output column 0..127
    int i0 = blockIdx.x * 128;
    float acc = 0.f;
#pragma unroll 4
    for (int i = 0; i < 128; i++)
        acc += x[i0 + i] * w1[(size_t)(i0 + i) * 128 + j];
    g_part[blockIdx.x * 128 + j] = acc;
}

__global__ void enc23_kernel(const float* __restrict__ b1,
                             const float* __restrict__ w2,
                             const float* __restrict__ b2,
                             const float* __restrict__ w3,
                             const float* __restrict__ b3) {
    __shared__ float h1s[128];
    __shared__ float h2s[64];
    int j = threadIdx.x;  // 128 threads
    float acc = b1[j];
    for (int b = 0; b < 64; b++) acc += g_part[b * 128 + j];
    h1s[j] = fmaxf(acc, 0.f);
    __syncthreads();
    if (j < 64) {
        float a2 = b2[j];
#pragma unroll 4
        for (int i = 0; i < 128; i++) a2 += h1s[i] * w2[i * 64 + j];
        h2s[j] = fmaxf(a2, 0.f);
    }
    __syncthreads();
    if (j < 2) {
        float p = b3[j];
        for (int i = 0; i < 64; i++) p += h2s[i] * w3[i * 2 + j];
        g_bg[j] = p;
    }
}

// ============================== ODE (dopri5) ================================
DINL float3 fsir(float3 y, float be, float ga) {
    float b = be * y.x * y.y;
    float g = ga * y.y;
    float3 r; r.x = -b; r.y = b - g; r.z = g;
    return r;
}
DINL float3 mad3(float3 a, float s, float3 b) {
    a.x = fmaf(s, b.x, a.x); a.y = fmaf(s, b.y, a.y); a.z = fmaf(s, b.z, a.z);
    return a;
}
DINL float3 dp5(float3 y, float h, float be, float ga) {
    const float A21 = 0.2f;
    const float A31 = (float)(3.0 / 40.0), A32 = (float)(9.0 / 40.0);
    const float A41 = (float)(44.0 / 45.0), A42 = (float)(-56.0 / 15.0), A43 = (float)(32.0 / 9.0);
    const float A51 = (float)(19372.0 / 6561.0), A52 = (float)(-25360.0 / 2187.0),
                A53 = (float)(64448.0 / 6561.0), A54 = (float)(-212.0 / 729.0);
    const float A61 = (float)(9017.0 / 3168.0), A62 = (float)(-355.0 / 33.0),
                A63 = (float)(46732.0 / 5247.0), A64 = (float)(49.0 / 176.0),
                A65 = (float)(-5103.0 / 18656.0);
    const float B1 = (float)(35.0 / 384.0), B3 = (float)(500.0 / 1113.0),
                B4 = (float)(125.0 / 192.0), B5 = (float)(-2187.0 / 6784.0),
                B6 = (float)(11.0 / 84.0);
    float3 k1 = fsir(y, be, ga);
    float3 yt = mad3(y, h * A21, k1);
    float3 k2 = fsir(yt, be, ga);
    yt = mad3(mad3(y, h * A31, k1), h * A32, k2);
    float3 k3 = fsir(yt, be, ga);
    yt = mad3(mad3(mad3(y, h * A41, k1), h * A42, k2), h * A43, k3);
    float3 k4 = fsir(yt, be, ga);
    yt = mad3(mad3(mad3(mad3(y, h * A51, k1), h * A52, k2), h * A53, k3), h * A54, k4);
    float3 k5 = fsir(yt, be, ga);
    yt = mad3(mad3(mad3(mad3(mad3(y, h * A61, k1), h * A62, k2), h * A63, k3), h * A64, k4),
              h * A65, k5);
    float3 k6 = fsir(yt, be, ga);
    float3 o = mad3(y, h * B1, k1);
    o = mad3(o, h * B3, k3);
    o = mad3(o, h * B4, k4);
    o = mad3(o, h * B5, k5);
    o = mad3(o, h * B6, k6);
    return o;
}

DINL int clampi(int i) { return i < 8191 ? i : 8191; }

__global__ void ode_kernel(const float* __restrict__ t) {
    __shared__ float3 super_s[16];
    __shared__ float3 chunk_s[512];
    const float be = g_bg[0], ga = g_bg[1];
    int tid = threadIdx.x;  // 512 threads

    // Level 1: 16 super-spans of 512 intervals; 1 dopri5 step each (h ~ 0.625).
    if (tid == 0) {
        float3 y; y.x = 0.99f; y.y = 0.01f; y.z = 0.f;
        for (int s = 0; s < 16; s++) {
            super_s[s] = y;
            if (s < 15) {
                float h = t[clampi((s + 1) * 512)] - t[s * 512];
                y = dp5(y, h, be, ga);
            }
        }
    }
    __syncthreads();

    // Level 2: 16 threads x 32 chunks of 16 intervals each.
    if (tid < 16) {
        float3 y = super_s[tid];
        int base = tid * 512;
        for (int c = 0; c < 32; c++) {
            chunk_s[tid * 32 + c] = y;
            float h = t[clampi(base + (c + 1) * 16)] - t[clampi(base + c * 16)];
            y = dp5(y, h, be, ga);
        }
    }
    __syncthreads();

    // Level 3: 512 threads x 16 single-interval steps, writing every grid state.
    {
        float3 y = chunk_s[tid];
        int base = tid * 16;
        if (tid == 0) { g_sol[0] = y.x; g_sol[1] = y.y; g_sol[2] = y.z; }
        for (int i = 0; i < 16; i++) {
            int gi = base + i + 1;
            if (gi <= 8191) {
                float h = t[gi] - t[gi - 1];
                y = dp5(y, h, be, ga);
                g_sol[gi * 3 + 0] = y.x;
                g_sol[gi * 3 + 1] = y.y;
                g_sol[gi * 3 + 2] = y.z;
            }
        }
    }
}

// ============================== decoder layers 1-2 ==========================
__global__ void dec12_kernel(const float* __restrict__ w1, const float* __restrict__ b1,
                             const float* __restrict__ w2, const float* __restrict__ b2) {
    __shared__ float h1s[4][64];
    int sub = threadIdx.x >> 6;           // 0..3
    int j = threadIdx.x & 63;             // 0..63
    int row = blockIdx.x * 4 + sub;
    float S = g_sol[row * 3 + 0], I = g_sol[row * 3 + 1], R = g_sol[row * 3 + 2];
    float a = S * w1[j] + I * w1[64 + j] + R * w1[128 + j] + b1[j];
    h1s[sub][j] = fmaxf(a, 0.f);
    __syncthreads();
    float acc0 = b2[j], acc1 = b2[j + 64];
#pragma unroll 4
    for (int i = 0; i < 64; i++) {
        float h = h1s[sub][i];
        acc0 = fmaf(h, w2[i * 128 + j], acc0);
        acc1 = fmaf(h, w2[i * 128 + j + 64], acc1);
    }
    acc0 = fmaxf(acc0, 0.f);
    acc1 = fmaxf(acc1, 0.f);
    __nv_bfloat16 hi0 = __float2bfloat16(acc0);
    __nv_bfloat16 hi1 = __float2bfloat16(acc1);
    g_h2_hi[row * 128 + j] = hi0;
    g_h2_hi[row * 128 + j + 64] = hi1;
    g_h2_lo[row * 128 + j] = __float2bfloat16(acc0 - __bfloat162float(hi0));
    g_h2_lo[row * 128 + j + 64] = __float2bfloat16(acc1 - __bfloat162float(hi1));
}

// ============================== W3 transpose + split ========================
__global__ void w3prep_kernel(const float* __restrict__ w3) {
    // w3 [128][8192] -> g_w3t [8192][128] (bf16 hi/lo)
    __shared__ float tile[32][33];
    int n0 = blockIdx.x * 32;
    int k0 = blockIdx.y * 32;
    int tx = threadIdx.x & 31;
    int ty = threadIdx.x >> 5;  // 0..7
    for (int r = ty; r < 32; r += 8)
        tile[r][tx] = w3[(size_t)(k0 + r) * 8192 + n0 + tx];
    __syncthreads();
    for (int r = ty; r < 32; r += 8) {
        float v = tile[tx][r];          // value at (k = k0+tx, n = n0+r)
        __nv_bfloat16 hi = __float2bfloat16(v);
        size_t o = (size_t)(n0 + r) * 128 + k0 + tx;
        g_w3t_hi[o] = hi;
        g_w3t_lo[o] = __float2bfloat16(v - __bfloat162float(hi));
    }
}

// ============================== GEMM (mma.sync bf16, 3-pass hi/lo) ==========
// CTA tile 128(M) x 128(N), K=128 fully resident in SMEM.
// SMEM arrays (each 128 rows x 256B, 16B-chunk XOR swizzle): A_hi, A_lo, B_hi, B_lo.
static const int SM_A_HI = 0;
static const int SM_A_LO = 32768;
static const int SM_B_HI = 65536;
static const int SM_B_LO = 98304;
static const int SM_TOTAL = 131072;

DINL uint32_t smem_u32(const void* p) { return (uint32_t)__cvta_generic_to_shared(p); }

// swizzled byte offset within one array: row (0..127), chunk cc (0..15, 16B units)
DINL uint32_t swz(int row, int cc) {
    return (uint32_t)row * 256u + (uint32_t)((cc ^ (row & 7)) << 4);
}

DINL void cp16(uint32_t dst, const void* src) {
    asm volatile("cp.async.cg.shared.global [%0], [%1], 16;" :: "r"(dst), "l"(src));
}

DINL void ldsm_x4(uint32_t& r0, uint32_t& r1, uint32_t& r2, uint32_t& r3, uint32_t addr) {
    asm volatile("ldmatrix.sync.aligned.m8n8.x4.shared.b16 {%0,%1,%2,%3}, [%4];"
                 : "=r"(r0), "=r"(r1), "=r"(r2), "=r"(r3) : "r"(addr));
}

DINL void mma16816(float* d, const uint32_t* a, const uint32_t* b) {
    asm volatile(
        "mma.sync.aligned.m16n8k16.row.col.f32.bf16.bf16.f32 "
        "{%0,%1,%2,%3}, {%4,%5,%6,%7}, {%8,%9}, {%0,%1,%2,%3};"
        : "+f"(d[0]), "+f"(d[1]), "+f"(d[2]), "+f"(d[3])
        : "r"(a[0]), "r"(a[1]), "r"(a[2]), "r"(a[3]), "r"(b[0]), "r"(b[1]));
}

__global__ void __launch_bounds__(256, 1)
gemm_kernel(const float* __restrict__ b3, float* __restrict__ out) {
    extern __shared__ char smem[];
    const uint32_t sb = smem_u32(smem);
    const int tid = threadIdx.x;
    const int lane = tid & 31;
    const int wid = tid >> 5;
    const int wm = wid & 3;     // warp M index (32 rows each)
    const int wn = wid >> 2;    // warp N index (64 cols each)

    const int m_base = blockIdx.x * 128;
    const int n_base = blockIdx.y * 128;

    const char* srcAH = (const char*)g_h2_hi + (size_t)m_base * 256;
    const char* srcAL = (const char*)g_h2_lo + (size_t)m_base * 256;
    const char* srcBH = (const char*)g_w3t_hi + (size_t)n_base * 256;
    const char* srcBL = (const char*)g_w3t_lo + (size_t)n_base * 256;

    // Issue cp.async in two K-halves (chunks 0-7, then 8-15), one commit group each.
#pragma unroll
    for (int half = 0; half < 2; half++) {
        // each array: 128 rows x 8 chunks = 1024 chunk-copies -> 4 per thread
#pragma unroll
        for (int i = 0; i < 4; i++) {
            int idx = tid + i * 256;          // 0..1023
            int r = idx >> 3;
            int cc = (idx & 7) + half * 8;
            uint32_t d = swz(r, cc);
            size_t s = (size_t)r * 256 + (size_t)cc * 16;
            cp16(sb + SM_A_HI + d, srcAH + s);
            cp16(sb + SM_A_LO + d, srcAL + s);
            cp16(sb + SM_B_HI + d, srcBH + s);
            cp16(sb + SM_B_LO + d, srcBL + s);
        }
        asm volatile("cp.async.commit_group;");
    }

    float acc[2][8][4];
#pragma unroll
    for (int mt = 0; mt < 2; mt++)
#pragma unroll
        for (int nt = 0; nt < 8; nt++)
#pragma unroll
            for (int c = 0; c < 4; c++) acc[mt][nt][c] = 0.f;

    // ldmatrix per-lane address components
    const int a_row = wm * 32 + (lane & 15);       // + mt*16
    const int a_ccs = (lane >> 4) & 1;             // chunk +0/+1
    const int b_row = wn * 64 + ((lane >> 4) & 1) * 8 + (lane & 7);  // + nt2*16
    const int b_ccs = (lane >> 3) & 1;

#pragma unroll
    for (int half = 0; half < 2; half++) {
        if (half == 0) asm volatile("cp.async.wait_group 1;");
        else           asm volatile("cp.async.wait_group 0;");
        __syncthreads();

#pragma unroll
        for (int pass = 0; pass < 3; pass++) {
            const uint32_t aB = sb + ((pass == 2) ? SM_A_LO : SM_A_HI);
            const uint32_t bB = sb + ((pass == 1) ? SM_B_LO : SM_B_HI);
#pragma unroll
            for (int k8 = 0; k8 < 4; k8++) {
                int ks = half * 4 + k8;
                int cc0 = ks * 2;
                uint32_t af[2][4];
#pragma unroll
                for (int mt = 0; mt < 2; mt++)
                    ldsm_x4(af[mt][0], af[mt][1], af[mt][2], af[mt][3],
                            aB + swz(a_row + mt * 16, cc0 + a_ccs));
                uint32_t bf[8][2];
#pragma unroll
                for (int nt2 = 0; nt2 < 4; nt2++) {
                    uint32_t r0, r1, r2, r3;
                    ldsm_x4(r0, r1, r2, r3,
                            bB + swz(b_row + nt2 * 16, cc0 + b_ccs));
                    bf[nt2 * 2][0] = r0; bf[nt2 * 2][1] = r1;
                    bf[nt2 * 2 + 1][0] = r2; bf[nt2 * 2 + 1][1] = r3;
                }
#pragma unroll
                for (int mt = 0; mt < 2; mt++)
#pragma unroll
                    for (int nt = 0; nt < 8; nt++)
                        mma16816(acc[mt][nt], af[mt], bf[nt]);
            }
        }
        if (half == 0) __syncthreads();  // keep halves coherent (smem reused? no, but cheap)
    }

    // Epilogue: bias + relu, direct float2 stores (full 32B sectors per warp op)
    const int g = lane >> 2;
    const int q = lane & 3;
#pragma unroll
    for (int mt = 0; mt < 2; mt++) {
#pragma unroll
        for (int nt = 0; nt < 8; nt++) {
            int col = n_base + wn * 64 + nt * 8 + q * 2;
            float bi0 = b3[col], bi1 = b3[col + 1];
#pragma unroll
            for (int h = 0; h < 2; h++) {
                int row = m_base + wm * 32 + mt * 16 + g + h * 8;
                float2 v;
                v.x = fmaxf(acc[mt][nt][h * 2 + 0] + bi0, 0.f);
                v.y = fmaxf(acc[mt][nt][h * 2 + 1] + bi1, 0.f);
                *(float2*)(out + (size_t)row * 8192 + col) = v;
            }
        }
    }
}

// ============================== launch ======================================
extern "C" void kernel_launch(void* const* d_in, const int* in_sizes, int n_in,
                              void* d_out, int out_size) {
    const float* x      = (const float*)d_in[0];
    const float* t      = (const float*)d_in[1];
    const float* enc_w1 = (const float*)d_in[2];
    const float* enc_b1 = (const float*)d_in[3];
    const float* enc_w2 = (const float*)d_in[4];
    const float* enc_b2 = (const float*)d_in[5];
    const float* enc_w3 = (const float*)d_in[6];
    const float* enc_b3 = (const float*)d_in[7];
    const float* dec_w1 = (const float*)d_in[8];
    const float* dec_b1 = (const float*)d_in[9];
    const float* dec_w2 = (const float*)d_in[10];
    const float* dec_b2 = (const float*)d_in[11];
    const float* dec_w3 = (const float*)d_in[12];
    const float* dec_b3 = (const float*)d_in[13];
    float* out = (float*)d_out;

    enc1_kernel<<<64, 128>>>(x, enc_w1);
    enc23_kernel<<<1, 128>>>(enc_b1, enc_w2, enc_b2, enc_w3, enc_b3);
    ode_kernel<<<1, 512>>>(t);
    dec12_kernel<<<2048, 256>>>(dec_w1, dec_b1, dec_w2, dec_b2);
    {
        dim3 g(256, 4);
        w3prep_kernel<<<g, 256>>>(dec_w3);
    }
    static bool attr_set = false;
    if (!attr_set) {
        cudaFuncSetAttribute(gemm_kernel, cudaFuncAttributeMaxDynamicSharedMemorySize, SM_TOTAL);
        attr_set = true;
    }
    dim3 grid(64, 64);
    gemm_kernel<<<grid, 256, SM_TOTAL>>>(dec_b3, out);
}